// round 5
// baseline (speedup 1.0000x reference)
#include <cuda_runtime.h>
#include <cuda_bf16.h>
#include <cstdint>

// RBF kernel matrix: out[i,j] = v * exp(min(cross_ij - hx_i - hy_j, 0))
// cross via classic mma.sync m16n8k16 bf16, 3-term hi/lo split
// (hi*hi + hi*lo + lo*hi). N = M = 8192, D = 64. Output fp32 [N, M].
// R5: 64x64 warp tiles (4 warps/CTA, 128x128 CTA tile) to halve LDSM per
// output; clamp dropped (analytically d2>=0, split error ~3e-5 << 1e-3).

#define NROWS 8192
#define MROWS 8192
#define DDIM  64

// ---------------- device scratch (allocation-free rule) ----------------
__device__ float g_invl[DDIM];
__device__ float g_v;
__device__ float g_lv;                            // log2(v)
__device__ float g_hxn[NROWS];                    // 0.5*||Xl_i||^2
__device__ float g_hyn[MROWS];                    // 0.5*||X2l_j||^2
__device__ __nv_bfloat16 g_Xhi[NROWS * DDIM];
__device__ __nv_bfloat16 g_Xlo[NROWS * DDIM];
__device__ __nv_bfloat16 g_Yhi[MROWS * DDIM];
__device__ __nv_bfloat16 g_Ylo[MROWS * DDIM];

// ---------------- helpers ----------------
__device__ __forceinline__ uint32_t smem_u32(const void* p) {
    uint32_t a;
    asm("{ .reg .u64 t; cvta.to.shared.u64 t, %1; cvt.u32.u64 %0, t; }"
        : "=r"(a) : "l"(p));
    return a;
}

__device__ __forceinline__ void ldsm_x4(uint32_t& r0, uint32_t& r1,
                                        uint32_t& r2, uint32_t& r3,
                                        uint32_t addr) {
    asm volatile("ldmatrix.sync.aligned.m8n8.x4.shared.b16 {%0,%1,%2,%3}, [%4];"
                 : "=r"(r0), "=r"(r1), "=r"(r2), "=r"(r3) : "r"(addr));
}

__device__ __forceinline__ void mma_bf16(float* c, const uint32_t* a,
                                         uint32_t b0, uint32_t b1) {
    asm volatile(
        "mma.sync.aligned.m16n8k16.row.col.f32.bf16.bf16.f32 "
        "{%0,%1,%2,%3}, {%4,%5,%6,%7}, {%8,%9}, {%0,%1,%2,%3};"
        : "+f"(c[0]), "+f"(c[1]), "+f"(c[2]), "+f"(c[3])
        : "r"(a[0]), "r"(a[1]), "r"(a[2]), "r"(a[3]), "r"(b0), "r"(b1));
}

__device__ __forceinline__ float fexp2(float x) {
    float r;
    asm("ex2.approx.f32 %0, %1;" : "=f"(r) : "f"(x));
    return r;
}

#define CP_ASYNC16(dst, src) \
    asm volatile("cp.async.cg.shared.global [%0], [%1], 16;" \
                 :: "r"(dst), "l"(src) : "memory")
#define CP_COMMIT() asm volatile("cp.async.commit_group;" ::: "memory")
#define CP_WAIT0()  asm volatile("cp.async.wait_group 0;" ::: "memory")

// ---------------------------------------------------------------------------
// Prep: softplus params, bf16 hi/lo split of scaled rows, half squared norms
// ---------------------------------------------------------------------------
__global__ void prep_kernel(const float* __restrict__ X,
                            const float* __restrict__ X2,
                            const float* __restrict__ ls,
                            const float* __restrict__ var) {
    __shared__ float invl_s[DDIM];
    int t = threadIdx.x;
    if (t < DDIM) {
        float r = ls[t];
        float l = fmaxf(r, 0.0f) + log1pf(expf(-fabsf(r)));
        float il = 1.0f / l;
        invl_s[t] = il;
        if (blockIdx.x == 0) g_invl[t] = il;
    }
    if (blockIdx.x == 0 && t == 64) {
        float r = var[0];
        float v = fmaxf(r, 0.0f) + log1pf(expf(-fabsf(r)));
        g_v = v;
        g_lv = log2f(v);
    }
    __syncthreads();

    int warp = t >> 5, lane = t & 31;
    int nwarps = blockDim.x >> 5;
    for (int row = blockIdx.x * nwarps + warp; row < NROWS + MROWS;
         row += gridDim.x * nwarps) {
        const float* src;
        __nv_bfloat16 *hi, *lo;
        int r;
        bool isX = (row < NROWS);
        if (isX) { r = row;         src = X  + (size_t)r * DDIM; hi = g_Xhi; lo = g_Xlo; }
        else     { r = row - NROWS; src = X2 + (size_t)r * DDIM; hi = g_Yhi; lo = g_Ylo; }
        float s = 0.0f;
        #pragma unroll
        for (int j = 0; j < 2; j++) {
            int d = lane + 32 * j;
            float xl = src[d] * invl_s[d];
            __nv_bfloat16 bh = __float2bfloat16(xl);
            __nv_bfloat16 bl = __float2bfloat16(xl - __bfloat162float(bh));
            hi[(size_t)r * DDIM + d] = bh;
            lo[(size_t)r * DDIM + d] = bl;
            s = fmaf(xl, xl, s);
        }
        #pragma unroll
        for (int off = 16; off; off >>= 1)
            s += __shfl_xor_sync(0xffffffffu, s, off);
        if (lane == 0) {
            if (isX) g_hxn[r] = 0.5f * s;
            else     g_hyn[r] = 0.5f * s;
        }
    }
}

// ---------------------------------------------------------------------------
// Main: 128x128 output tile per 128-thread CTA (4 warps, 2x2 grid of
// 64x64 warp tiles). Smem tiles [128 rows][64 bf16] = 128B rows, 16B-chunk
// XOR swizzle: phys_chunk = c ^ (row & 7) -> ldmatrix conflict-free.
// ---------------------------------------------------------------------------
#define SMEM_HX    0                   // 128 floats: hx*L2E - log2(v)
#define SMEM_HY    512                 // 128 floats: hy*L2E
#define SMEM_TILES 1024                // Xhi, Xlo, Yhi, Ylo: 16 KB each
#define TILE_BYTES 16384
#define SMEM_TOTAL (1024 + 4 * TILE_BYTES)

__global__ void __launch_bounds__(128, 2)
rbf_mma_kernel(float* __restrict__ out) {
    extern __shared__ char smem[];
    const uint32_t sb = smem_u32(smem);
    const int t = threadIdx.x;
    const int wid = t >> 5;
    const int lane = t & 31;

    const int x0 = blockIdx.y * 128;      // X rows (output rows)
    const int y0 = blockIdx.x * 128;      // X2 rows (output cols)

    const float L2E = 1.4426950408889634f;
    const float lv = g_lv;

    // Tile fill via cp.async (LDGSTS), swizzled. 4 tiles x 1024 chunks.
    {
        const uint4* srcs[4] = {
            (const uint4*)(g_Xhi + (size_t)x0 * DDIM),
            (const uint4*)(g_Xlo + (size_t)x0 * DDIM),
            (const uint4*)(g_Yhi + (size_t)y0 * DDIM),
            (const uint4*)(g_Ylo + (size_t)y0 * DDIM)
        };
        #pragma unroll
        for (int tile = 0; tile < 4; tile++) {
            uint32_t dstb = sb + SMEM_TILES + tile * TILE_BYTES;
            #pragma unroll
            for (int i = 0; i < 8; i++) {
                int id = t + i * 128;               // chunk id: row*8 + c
                int row = id >> 3, c = id & 7;
                uint32_t sw = (uint32_t)row * 128 + (uint32_t)((c ^ (row & 7)) * 16);
                CP_ASYNC16(dstb + sw, srcs[tile] + id);
            }
        }
        CP_COMMIT();
    }

    // Norm tiles (pre-scaled for folded epilogue)
    if (t < 128) {
        ((float*)(smem + SMEM_HX))[t] = g_hxn[x0 + t] * L2E - lv;
        ((float*)(smem + SMEM_HY))[t] = g_hyn[y0 + t] * L2E;
    }

    CP_WAIT0();
    __syncthreads();

    const uint32_t sXhi = sb + SMEM_TILES;
    const uint32_t sXlo = sXhi + TILE_BYTES;
    const uint32_t sYhi = sXlo + TILE_BYTES;
    const uint32_t sYlo = sYhi + TILE_BYTES;

    const int wy = wid & 1;               // m group: 64 rows
    const int wx = wid >> 1;              // n group: 64 cols
    const int mbase = wy * 64;
    const int nbase = wx * 64;

    // ldmatrix per-lane addressing
    const int lrow = lane & 15;
    const int lhalf = lane >> 4;
    const int lsw = lrow & 7;
    const uint32_t rowA = (uint32_t)(mbase + lrow) * 128;
    const uint32_t rowB = (uint32_t)(nbase + lrow) * 128;
    uint32_t kc[4];
    #pragma unroll
    for (int kb = 0; kb < 4; kb++)
        kc[kb] = (uint32_t)(((kb * 2 + lhalf) ^ lsw) * 16);

    // acc[mt][np][4]: mt = 16-row tile (4), np = 8-col tile (8)
    float acc[4][8][4];
    #pragma unroll
    for (int mt = 0; mt < 4; mt++)
        #pragma unroll
        for (int np = 0; np < 8; np++)
            #pragma unroll
            for (int f = 0; f < 4; f++)
                acc[mt][np][f] = 0.0f;

    #pragma unroll
    for (int kb = 0; kb < 4; kb++) {
        const uint32_t k = kc[kb];
        uint32_t bh[4][4], bl[4][4], ah[4][4], al[4][4];
        #pragma unroll
        for (int bp = 0; bp < 4; bp++)
            ldsm_x4(bh[bp][0], bh[bp][1], bh[bp][2], bh[bp][3],
                    sYhi + rowB + bp * 2048 + k);
        #pragma unroll
        for (int mt = 0; mt < 4; mt++)
            ldsm_x4(ah[mt][0], ah[mt][1], ah[mt][2], ah[mt][3],
                    sXhi + rowA + mt * 2048 + k);

        // term hi*hi
        #pragma unroll
        for (int mt = 0; mt < 4; mt++)
            #pragma unroll
            for (int bp = 0; bp < 4; bp++) {
                mma_bf16(acc[mt][bp * 2],     ah[mt], bh[bp][0], bh[bp][2]);
                mma_bf16(acc[mt][bp * 2 + 1], ah[mt], bh[bp][1], bh[bp][3]);
            }

        // load B-lo, then term hi*lo
        #pragma unroll
        for (int bp = 0; bp < 4; bp++)
            ldsm_x4(bl[bp][0], bl[bp][1], bl[bp][2], bl[bp][3],
                    sYlo + rowB + bp * 2048 + k);
        #pragma unroll
        for (int mt = 0; mt < 4; mt++)
            #pragma unroll
            for (int bp = 0; bp < 4; bp++) {
                mma_bf16(acc[mt][bp * 2],     ah[mt], bl[bp][0], bl[bp][2]);
                mma_bf16(acc[mt][bp * 2 + 1], ah[mt], bl[bp][1], bl[bp][3]);
            }

        // load A-lo, then term lo*hi
        #pragma unroll
        for (int mt = 0; mt < 4; mt++)
            ldsm_x4(al[mt][0], al[mt][1], al[mt][2], al[mt][3],
                    sXlo + rowA + mt * 2048 + k);
        #pragma unroll
        for (int mt = 0; mt < 4; mt++)
            #pragma unroll
            for (int bp = 0; bp < 4; bp++) {
                mma_bf16(acc[mt][bp * 2],     al[mt], bh[bp][0], bh[bp][2]);
                mma_bf16(acc[mt][bp * 2 + 1], al[mt], bh[bp][1], bh[bp][3]);
            }
    }

    // Epilogue: out = exp2(cross*L2E - hx' - hy'),
    //   hx' = hx*L2E - log2(v), hy' = hy*L2E.  (d2 >= 0 analytically; the
    //   bf16-split error ~3e-5 on the exponent makes clamping unnecessary.)
    const int g = lane >> 2;
    const int n2 = (lane & 3) * 2;
    const float* HX = (const float*)(smem + SMEM_HX);
    const float* HY = (const float*)(smem + SMEM_HY);

    #pragma unroll
    for (int mt = 0; mt < 4; mt++) {
        const int r0 = mbase + mt * 16 + g;
        const float hx0 = HX[r0];
        const float hx1 = HX[r0 + 8];
        #pragma unroll
        for (int np = 0; np < 8; np++) {
            const int cc = nbase + np * 8 + n2;
            const float hy0 = HY[cc];
            const float hy1 = HY[cc + 1];
            float* c = acc[mt][np];
            float2 o0, o1;
            o0.x = fexp2(fmaf(c[0], L2E, -hx0 - hy0));
            o0.y = fexp2(fmaf(c[1], L2E, -hx0 - hy1));
            o1.x = fexp2(fmaf(c[2], L2E, -hx1 - hy0));
            o1.y = fexp2(fmaf(c[3], L2E, -hx1 - hy1));
            *(float2*)(out + (size_t)(x0 + r0) * MROWS + y0 + cc)     = o0;
            *(float2*)(out + (size_t)(x0 + r0 + 8) * MROWS + y0 + cc) = o1;
        }
    }
}

// ---------------------------------------------------------------------------
extern "C" void kernel_launch(void* const* d_in, const int* in_sizes, int n_in,
                              void* d_out, int out_size) {
    const float* X   = (const float*)d_in[0];
    const float* X2  = (const float*)d_in[1];
    const float* ls  = (const float*)d_in[2];
    const float* var = (const float*)d_in[3];
    float* out = (float*)d_out;

    prep_kernel<<<512, 256>>>(X, X2, ls, var);

    cudaFuncSetAttribute(rbf_mma_kernel,
                         cudaFuncAttributeMaxDynamicSharedMemorySize, SMEM_TOTAL);
    dim3 grid(MROWS / 128, NROWS / 128);
    rbf_mma_kernel<<<grid, 128, SMEM_TOTAL>>>(out);
}

// round 6
// speedup vs baseline: 1.1425x; 1.1425x over previous
#include <cuda_runtime.h>
#include <cuda_bf16.h>
#include <cstdint>

// RBF kernel matrix: out[i,j] = v * exp(cross_ij - hx_i - hy_j)
// cross via classic mma.sync m16n8k16 bf16, 3-term hi/lo split
// (hi*hi + hi*lo + lo*hi). N = M = 8192, D = 64. Output fp32 [N, M].
// R6: 64x128 CTA tile, 128 threads (4 warps of 64x32), 4 CTAs/SM for
// cross-CTA stagger of epilogue (MUFU/STG) vs mainloop (HMMA).

#define NROWS 8192
#define MROWS 8192
#define DDIM  64

// ---------------- device scratch (allocation-free rule) ----------------
__device__ float g_invl[DDIM];
__device__ float g_v;
__device__ float g_lv;                            // log2(v)
__device__ float g_hxn[NROWS];                    // 0.5*||Xl_i||^2
__device__ float g_hyn[MROWS];                    // 0.5*||X2l_j||^2
__device__ __nv_bfloat16 g_Xhi[NROWS * DDIM];
__device__ __nv_bfloat16 g_Xlo[NROWS * DDIM];
__device__ __nv_bfloat16 g_Yhi[MROWS * DDIM];
__device__ __nv_bfloat16 g_Ylo[MROWS * DDIM];

// ---------------- helpers ----------------
__device__ __forceinline__ uint32_t smem_u32(const void* p) {
    uint32_t a;
    asm("{ .reg .u64 t; cvta.to.shared.u64 t, %1; cvt.u32.u64 %0, t; }"
        : "=r"(a) : "l"(p));
    return a;
}

__device__ __forceinline__ void ldsm_x4(uint32_t& r0, uint32_t& r1,
                                        uint32_t& r2, uint32_t& r3,
                                        uint32_t addr) {
    asm volatile("ldmatrix.sync.aligned.m8n8.x4.shared.b16 {%0,%1,%2,%3}, [%4];"
                 : "=r"(r0), "=r"(r1), "=r"(r2), "=r"(r3) : "r"(addr));
}

__device__ __forceinline__ void mma_bf16(float* c, const uint32_t* a,
                                         uint32_t b0, uint32_t b1) {
    asm volatile(
        "mma.sync.aligned.m16n8k16.row.col.f32.bf16.bf16.f32 "
        "{%0,%1,%2,%3}, {%4,%5,%6,%7}, {%8,%9}, {%0,%1,%2,%3};"
        : "+f"(c[0]), "+f"(c[1]), "+f"(c[2]), "+f"(c[3])
        : "r"(a[0]), "r"(a[1]), "r"(a[2]), "r"(a[3]), "r"(b0), "r"(b1));
}

__device__ __forceinline__ float fexp2(float x) {
    float r;
    asm("ex2.approx.f32 %0, %1;" : "=f"(r) : "f"(x));
    return r;
}

#define CP_ASYNC16(dst, src) \
    asm volatile("cp.async.cg.shared.global [%0], [%1], 16;" \
                 :: "r"(dst), "l"(src) : "memory")
#define CP_COMMIT() asm volatile("cp.async.commit_group;" ::: "memory")
#define CP_WAIT0()  asm volatile("cp.async.wait_group 0;" ::: "memory")

// ---------------------------------------------------------------------------
// Prep: softplus params, bf16 hi/lo split of scaled rows, half squared norms
// ---------------------------------------------------------------------------
__global__ void prep_kernel(const float* __restrict__ X,
                            const float* __restrict__ X2,
                            const float* __restrict__ ls,
                            const float* __restrict__ var) {
    __shared__ float invl_s[DDIM];
    int t = threadIdx.x;
    if (t < DDIM) {
        float r = ls[t];
        float l = fmaxf(r, 0.0f) + log1pf(expf(-fabsf(r)));
        float il = 1.0f / l;
        invl_s[t] = il;
        if (blockIdx.x == 0) g_invl[t] = il;
    }
    if (blockIdx.x == 0 && t == 64) {
        float r = var[0];
        float v = fmaxf(r, 0.0f) + log1pf(expf(-fabsf(r)));
        g_v = v;
        g_lv = log2f(v);
    }
    __syncthreads();

    int warp = t >> 5, lane = t & 31;
    int nwarps = blockDim.x >> 5;
    for (int row = blockIdx.x * nwarps + warp; row < NROWS + MROWS;
         row += gridDim.x * nwarps) {
        const float* src;
        __nv_bfloat16 *hi, *lo;
        int r;
        bool isX = (row < NROWS);
        if (isX) { r = row;         src = X  + (size_t)r * DDIM; hi = g_Xhi; lo = g_Xlo; }
        else     { r = row - NROWS; src = X2 + (size_t)r * DDIM; hi = g_Yhi; lo = g_Ylo; }
        float s = 0.0f;
        #pragma unroll
        for (int j = 0; j < 2; j++) {
            int d = lane + 32 * j;
            float xl = src[d] * invl_s[d];
            __nv_bfloat16 bh = __float2bfloat16(xl);
            __nv_bfloat16 bl = __float2bfloat16(xl - __bfloat162float(bh));
            hi[(size_t)r * DDIM + d] = bh;
            lo[(size_t)r * DDIM + d] = bl;
            s = fmaf(xl, xl, s);
        }
        #pragma unroll
        for (int off = 16; off; off >>= 1)
            s += __shfl_xor_sync(0xffffffffu, s, off);
        if (lane == 0) {
            if (isX) g_hxn[r] = 0.5f * s;
            else     g_hyn[r] = 0.5f * s;
        }
    }
}

// ---------------------------------------------------------------------------
// Main: 64(rows) x 128(cols) output tile per 128-thread CTA.
// 4 warps side-by-side along n; each warp computes 64x32 via
// mma.sync m16n8k16 (4 m-tiles x 4 n-tiles x 3 terms).
// Smem tiles: [rows][64 bf16] = 128B rows, 16B-chunk XOR swizzle
//   phys_chunk = c ^ (row & 7) -> ldmatrix conflict-free.
// ---------------------------------------------------------------------------
#define SMEM_HX    0                   // 64 floats:  hx*L2E - log2(v)
#define SMEM_HY    256                 // 128 floats: hy*L2E
#define SMEM_TILES 1024
#define XT_BYTES   8192                // 64 rows * 128B
#define YT_BYTES   16384               // 128 rows * 128B
#define SMEM_TOTAL (1024 + 2 * XT_BYTES + 2 * YT_BYTES)

__global__ void __launch_bounds__(128, 4)
rbf_mma_kernel(float* __restrict__ out) {
    extern __shared__ char smem[];
    const uint32_t sb = smem_u32(smem);
    const int t = threadIdx.x;
    const int wid = t >> 5;
    const int lane = t & 31;

    const int x0 = blockIdx.y * 64;       // X rows (output rows)
    const int y0 = blockIdx.x * 128;      // X2 rows (output cols)

    const float L2E = 1.4426950408889634f;
    const float lv = g_lv;

    const uint32_t sXhi = sb + SMEM_TILES;
    const uint32_t sXlo = sXhi + XT_BYTES;
    const uint32_t sYhi = sXlo + XT_BYTES;
    const uint32_t sYlo = sYhi + YT_BYTES;

    // Tile fill via cp.async (LDGSTS), swizzled.
    {
        const uint4* srcX[2] = {
            (const uint4*)(g_Xhi + (size_t)x0 * DDIM),
            (const uint4*)(g_Xlo + (size_t)x0 * DDIM)
        };
        const uint4* srcY[2] = {
            (const uint4*)(g_Yhi + (size_t)y0 * DDIM),
            (const uint4*)(g_Ylo + (size_t)y0 * DDIM)
        };
        #pragma unroll
        for (int tile = 0; tile < 2; tile++) {
            uint32_t dstb = sXhi + tile * XT_BYTES;
            #pragma unroll
            for (int i = 0; i < 4; i++) {          // 512 chunks / 128 thr
                int id = t + i * 128;
                int row = id >> 3, c = id & 7;
                uint32_t sw = (uint32_t)row * 128 + (uint32_t)((c ^ (row & 7)) * 16);
                CP_ASYNC16(dstb + sw, srcX[tile] + id);
            }
        }
        #pragma unroll
        for (int tile = 0; tile < 2; tile++) {
            uint32_t dstb = sYhi + tile * YT_BYTES;
            #pragma unroll
            for (int i = 0; i < 8; i++) {          // 1024 chunks / 128 thr
                int id = t + i * 128;
                int row = id >> 3, c = id & 7;
                uint32_t sw = (uint32_t)row * 128 + (uint32_t)((c ^ (row & 7)) * 16);
                CP_ASYNC16(dstb + sw, srcY[tile] + id);
            }
        }
        CP_COMMIT();
    }

    // Norm tiles (pre-scaled for folded epilogue)
    if (t < 64) ((float*)(smem + SMEM_HX))[t] = g_hxn[x0 + t] * L2E - lv;
    ((float*)(smem + SMEM_HY))[t] = g_hyn[y0 + t] * L2E;

    CP_WAIT0();
    __syncthreads();

    const int nbase = wid * 32;           // warp's 32 output cols

    // ldmatrix per-lane addressing
    const int lrow = lane & 15;
    const int lhalf = lane >> 4;
    const int lsw = lrow & 7;
    const uint32_t rowA = (uint32_t)lrow * 128;
    const uint32_t rowB = (uint32_t)(nbase + lrow) * 128;
    uint32_t kc[4];
    #pragma unroll
    for (int kb = 0; kb < 4; kb++)
        kc[kb] = (uint32_t)(((kb * 2 + lhalf) ^ lsw) * 16);

    float acc[4][4][4];
    #pragma unroll
    for (int mt = 0; mt < 4; mt++)
        #pragma unroll
        for (int nt = 0; nt < 4; nt++)
            #pragma unroll
            for (int f = 0; f < 4; f++)
                acc[mt][nt][f] = 0.0f;

    #pragma unroll
    for (int kb = 0; kb < 4; kb++) {
        const uint32_t k = kc[kb];
        uint32_t bh[2][4], bl[2][4], ah[4][4], al[4][4];
        #pragma unroll
        for (int bp = 0; bp < 2; bp++) {
            ldsm_x4(bh[bp][0], bh[bp][1], bh[bp][2], bh[bp][3],
                    sYhi + rowB + bp * 2048 + k);
            ldsm_x4(bl[bp][0], bl[bp][1], bl[bp][2], bl[bp][3],
                    sYlo + rowB + bp * 2048 + k);
        }
        #pragma unroll
        for (int mt = 0; mt < 4; mt++)
            ldsm_x4(ah[mt][0], ah[mt][1], ah[mt][2], ah[mt][3],
                    sXhi + rowA + mt * 2048 + k);

        // term hi*hi
        #pragma unroll
        for (int mt = 0; mt < 4; mt++) {
            mma_bf16(acc[mt][0], ah[mt], bh[0][0], bh[0][2]);
            mma_bf16(acc[mt][1], ah[mt], bh[0][1], bh[0][3]);
            mma_bf16(acc[mt][2], ah[mt], bh[1][0], bh[1][2]);
            mma_bf16(acc[mt][3], ah[mt], bh[1][1], bh[1][3]);
        }
        // load A-lo while hi*lo MMAs run
        #pragma unroll
        for (int mt = 0; mt < 4; mt++)
            ldsm_x4(al[mt][0], al[mt][1], al[mt][2], al[mt][3],
                    sXlo + rowA + mt * 2048 + k);
        // term hi*lo
        #pragma unroll
        for (int mt = 0; mt < 4; mt++) {
            mma_bf16(acc[mt][0], ah[mt], bl[0][0], bl[0][2]);
            mma_bf16(acc[mt][1], ah[mt], bl[0][1], bl[0][3]);
            mma_bf16(acc[mt][2], ah[mt], bl[1][0], bl[1][2]);
            mma_bf16(acc[mt][3], ah[mt], bl[1][1], bl[1][3]);
        }
        // term lo*hi
        #pragma unroll
        for (int mt = 0; mt < 4; mt++) {
            mma_bf16(acc[mt][0], al[mt], bh[0][0], bh[0][2]);
            mma_bf16(acc[mt][1], al[mt], bh[0][1], bh[0][3]);
            mma_bf16(acc[mt][2], al[mt], bh[1][0], bh[1][2]);
            mma_bf16(acc[mt][3], al[mt], bh[1][1], bh[1][3]);
        }
    }

    // Epilogue: out = exp2(cross*L2E - hx' - hy'),
    //   hx' = hx*L2E - log2(v), hy' = hy*L2E.  (d2 >= 0 analytically; the
    //   bf16-split error ~3e-5 on the exponent makes clamping unnecessary.)
    const int g = lane >> 2;
    const int n2 = (lane & 3) * 2;
    const float* HX = (const float*)(smem + SMEM_HX);
    const float* HY = (const float*)(smem + SMEM_HY);

    #pragma unroll
    for (int mt = 0; mt < 4; mt++) {
        const int r0 = mt * 16 + g;
        const float hx0 = HX[r0];
        const float hx1 = HX[r0 + 8];
        #pragma unroll
        for (int nt = 0; nt < 4; nt++) {
            const int cc = nbase + nt * 8 + n2;
            const float hy0 = HY[cc];
            const float hy1 = HY[cc + 1];
            float* c = acc[mt][nt];
            float2 o0, o1;
            o0.x = fexp2(fmaf(c[0], L2E, -hx0 - hy0));
            o0.y = fexp2(fmaf(c[1], L2E, -hx0 - hy1));
            o1.x = fexp2(fmaf(c[2], L2E, -hx1 - hy0));
            o1.y = fexp2(fmaf(c[3], L2E, -hx1 - hy1));
            *(float2*)(out + (size_t)(x0 + r0) * MROWS + y0 + cc)     = o0;
            *(float2*)(out + (size_t)(x0 + r0 + 8) * MROWS + y0 + cc) = o1;
        }
    }
}

// ---------------------------------------------------------------------------
extern "C" void kernel_launch(void* const* d_in, const int* in_sizes, int n_in,
                              void* d_out, int out_size) {
    const float* X   = (const float*)d_in[0];
    const float* X2  = (const float*)d_in[1];
    const float* ls  = (const float*)d_in[2];
    const float* var = (const float*)d_in[3];
    float* out = (float*)d_out;

    prep_kernel<<<512, 256>>>(X, X2, ls, var);

    cudaFuncSetAttribute(rbf_mma_kernel,
                         cudaFuncAttributeMaxDynamicSharedMemorySize, SMEM_TOTAL);
    dim3 grid(MROWS / 128, NROWS / 64);
    rbf_mma_kernel<<<grid, 128, SMEM_TOTAL>>>(out);
}